// round 7
// baseline (speedup 1.0000x reference)
#include <cuda_runtime.h>
#include <cuda_bf16.h>

#define N_PTS   32768
#define S_NBR   32
#define C_IN    64
#define C_OUT   128
#define NS      (N_PTS * S_NBR)   // 1048576
#define EPSBN   1e-5f

// Scratch (device globals; no allocation allowed)
__device__ float g_ypre[C_OUT * N_PTS];   // [o][n] 16 MB  (feature pre-BN)
__device__ float g_rpre[C_OUT * N_PTS];   // [o][n] 16 MB  (residual pre-BN)
__device__ float g_stats[4 * C_OUT];      // [sum_f | sumsq_f | sum_r | sumsq_r]

// ---------------------------------------------------------------------------
__global__ void k_zero_stats() {
    g_stats[threadIdx.x] = 0.0f;
}

// ---------------------------------------------------------------------------
// Fully fused kernel (R5 structure + in-kernel BN statistics).
// Block = 256 threads, 32 points. 3 CTAs/SM target.
//
// Phase 1 (aggregation): lane = (idx = lane>>3, s4 = lane&7).
//   Warp w owns channels [8w, 8w+8). Point-group outer (positions register-
//   resident), channel inner. LDG.128 per warp = 512B contiguous.
//   3-shfl reduce over the 8-lane s4 group.
// Phase 2 (feature GEMV 64->128): warp = 16-output slab, lane = point.
//   After GEMV: per-output lane-reduction of sum/sumsq -> global atomicAdd.
// Phase 3 (residual GEMV): same tiling + stats, smem reloaded.
__global__ __launch_bounds__(256, 3) void k_fused(
    const float* __restrict__ xyz,     // [N][3]
    const float* __restrict__ np,      // [67][N][S]
    const float* __restrict__ pf,      // [64][N]
    const float* __restrict__ Wint,    // [64][3]
    const float* __restrict__ bint,    // [64]
    const float* __restrict__ Wfeat,   // [128][64]
    const float* __restrict__ bfeat,   // [128]
    const float* __restrict__ Wres,    // [128][64]
    const float* __restrict__ bres)    // [128]
{
    __shared__ __align__(16) float spos[3 * 32 * 32];  // 12 KB: [k][pt][s]
    __shared__ float  aggs[C_IN][33];                  // padded; reused as pf tile
    __shared__ float4 Ws[C_OUT * (C_IN/4)];            // 32 KB
    __shared__ float  bs[C_OUT];
    __shared__ float4 wq[C_IN];                        // {w0,w1,w2,bias}

    int tid  = threadIdx.x;
    int warp = tid >> 5;
    int lane = tid & 31;
    int n0   = blockIdx.x * 32;

    // ---- stage Wint + Wfeat + relative positions ----
    if (tid < C_IN)
        wq[tid] = make_float4(Wint[tid*3+0], Wint[tid*3+1], Wint[tid*3+2], bint[tid]);
    {
        const float4* W4 = (const float4*)Wfeat;
        #pragma unroll
        for (int i = tid; i < C_OUT * (C_IN/4); i += 256) Ws[i] = W4[i];
        if (tid < C_OUT) bs[tid] = bfeat[tid];
    }
    #pragma unroll
    for (int i = tid; i < 3 * 1024; i += 256) {
        int k  = i >> 10;          // coord 0..2
        int r  = i & 1023;         // pt*32 + s
        int pt = r >> 5;
        spos[i] = np[k * NS + (n0 << 5) + r] - xyz[(n0 + pt) * 3 + k];
    }
    __syncthreads();

    // ---- Phase 1: aggregation (positions register-resident) ----
    {
        int s4  = lane & 7;        // 16B chunk within a 128B s-line
        int idx = lane >> 3;       // point within group of 4
        int c0  = warp << 3;       // first channel this warp owns
        const float4* sp4 = (const float4*)spos;

        #pragma unroll
        for (int ptg = 0; ptg < 8; ptg++) {
            int pt = (ptg << 2) | idx;
            float4 px = sp4[0 * 256 + (pt << 3) + s4];
            float4 py = sp4[1 * 256 + (pt << 3) + s4];
            float4 pz = sp4[2 * 256 + (pt << 3) + s4];

            const float* fb = np + (size_t)3 * NS
                            + (((size_t)(n0 + pt)) << 5) + (s4 << 2);

            #pragma unroll
            for (int ci = 0; ci < 8; ci++) {
                int c = c0 | ci;
                float4 w = wq[c];                                  // broadcast
                float4 f = *(const float4*)(fb + (size_t)c * NS);  // 512B/warp

                float h0 = fmaf(w.x, px.x, fmaf(w.y, py.x, fmaf(w.z, pz.x, w.w)));
                float h1 = fmaf(w.x, px.y, fmaf(w.y, py.y, fmaf(w.z, pz.y, w.w)));
                float h2 = fmaf(w.x, px.z, fmaf(w.y, py.z, fmaf(w.z, pz.z, w.w)));
                float h3 = fmaf(w.x, px.w, fmaf(w.y, py.w, fmaf(w.z, pz.w, w.w)));

                float acc;
                acc = fmaxf(h0, 0.0f) * f.x;
                acc = fmaf(fmaxf(h1, 0.0f), f.y, acc);
                acc = fmaf(fmaxf(h2, 0.0f), f.z, acc);
                acc = fmaf(fmaxf(h3, 0.0f), f.w, acc);

                acc += __shfl_xor_sync(0xffffffffu, acc, 1);
                acc += __shfl_xor_sync(0xffffffffu, acc, 2);
                acc += __shfl_xor_sync(0xffffffffu, acc, 4);
                if (s4 == 0) aggs[c][pt] = acc;
            }
        }
    }
    __syncthreads();

    // ---- Phase 2: feature GEMV + stats ----
    int o0 = warp * 16;
    {
        float acc[16];
        #pragma unroll
        for (int oi = 0; oi < 16; oi++) acc[oi] = bs[o0 + oi];

        #pragma unroll 4
        for (int c4 = 0; c4 < C_IN/4; c4++) {
            float f0 = aggs[c4*4+0][lane];
            float f1 = aggs[c4*4+1][lane];
            float f2 = aggs[c4*4+2][lane];
            float f3 = aggs[c4*4+3][lane];
            #pragma unroll
            for (int oi = 0; oi < 16; oi++) {
                float4 w4 = Ws[(o0 + oi) * (C_IN/4) + c4];
                acc[oi] = fmaf(f0, w4.x, acc[oi]);
                acc[oi] = fmaf(f1, w4.y, acc[oi]);
                acc[oi] = fmaf(f2, w4.z, acc[oi]);
                acc[oi] = fmaf(f3, w4.w, acc[oi]);
            }
        }
        int n = n0 + lane;
        #pragma unroll
        for (int oi = 0; oi < 16; oi++)
            g_ypre[(o0 + oi) * N_PTS + n] = acc[oi];   // coalesced

        // per-output block sums -> global atomics (stats for BN)
        #pragma unroll
        for (int oi = 0; oi < 16; oi++) {
            float s1 = acc[oi];
            float s2 = acc[oi] * acc[oi];
            #pragma unroll
            for (int off = 16; off; off >>= 1) {
                s1 += __shfl_xor_sync(0xffffffffu, s1, off);
                s2 += __shfl_xor_sync(0xffffffffu, s2, off);
            }
            if (lane == 0) {
                atomicAdd(&g_stats[o0 + oi], s1);
                atomicAdd(&g_stats[C_OUT + o0 + oi], s2);
            }
        }
    }
    __syncthreads();   // done reading aggs/Ws before overwrite

    // ---- reload smem with residual operands ----
    {
        const float4* W4 = (const float4*)Wres;
        #pragma unroll
        for (int i = tid; i < C_OUT * (C_IN/4); i += 256) Ws[i] = W4[i];
        if (tid < C_OUT) bs[tid] = bres[tid];
    }
    #pragma unroll
    for (int i = tid; i < C_IN * 32; i += 256) {
        int cc = i >> 5, col = i & 31;
        aggs[cc][col] = pf[cc * N_PTS + n0 + col];   // coalesced
    }
    __syncthreads();

    // ---- Phase 3: residual GEMV + stats ----
    {
        float acc[16];
        #pragma unroll
        for (int oi = 0; oi < 16; oi++) acc[oi] = bs[o0 + oi];

        #pragma unroll 4
        for (int c4 = 0; c4 < C_IN/4; c4++) {
            float f0 = aggs[c4*4+0][lane];
            float f1 = aggs[c4*4+1][lane];
            float f2 = aggs[c4*4+2][lane];
            float f3 = aggs[c4*4+3][lane];
            #pragma unroll
            for (int oi = 0; oi < 16; oi++) {
                float4 w4 = Ws[(o0 + oi) * (C_IN/4) + c4];
                acc[oi] = fmaf(f0, w4.x, acc[oi]);
                acc[oi] = fmaf(f1, w4.y, acc[oi]);
                acc[oi] = fmaf(f2, w4.z, acc[oi]);
                acc[oi] = fmaf(f3, w4.w, acc[oi]);
            }
        }
        int n = n0 + lane;
        #pragma unroll
        for (int oi = 0; oi < 16; oi++)
            g_rpre[(o0 + oi) * N_PTS + n] = acc[oi];

        #pragma unroll
        for (int oi = 0; oi < 16; oi++) {
            float s1 = acc[oi];
            float s2 = acc[oi] * acc[oi];
            #pragma unroll
            for (int off = 16; off; off >>= 1) {
                s1 += __shfl_xor_sync(0xffffffffu, s1, off);
                s2 += __shfl_xor_sync(0xffffffffu, s2, off);
            }
            if (lane == 0) {
                atomicAdd(&g_stats[2*C_OUT + o0 + oi], s1);
                atomicAdd(&g_stats[3*C_OUT + o0 + oi], s2);
            }
        }
    }
}

// ---------------------------------------------------------------------------
// Finalize: BN coefficients inline from g_stats, affine + ReLU both paths,
// add, float4 throughout.
__global__ __launch_bounds__(256) void k_final(
    const float* __restrict__ gf, const float* __restrict__ btf,
    const float* __restrict__ gr, const float* __restrict__ btr,
    float* __restrict__ out)
{
    int i4 = blockIdx.x * 256 + threadIdx.x;    // float4 index
    int o  = i4 >> 13;                          // channel (N/4 = 8192 per row)
    const float inv = 1.0f / (float)N_PTS;

    float mf = g_stats[o] * inv;
    float vf = g_stats[C_OUT + o] * inv - mf * mf;
    float Af = gf[o] * rsqrtf(vf + EPSBN);
    float Bf = btf[o] - mf * Af;

    float mr = g_stats[2*C_OUT + o] * inv;
    float vr = g_stats[3*C_OUT + o] * inv - mr * mr;
    float Ar = gr[o] * rsqrtf(vr + EPSBN);
    float Br = btr[o] - mr * Ar;

    float4 y = ((const float4*)g_ypre)[i4];
    float4 r = ((const float4*)g_rpre)[i4];
    float4 v;
    v.x = fmaxf(fmaf(y.x, Af, Bf), 0.0f) + fmaxf(fmaf(r.x, Ar, Br), 0.0f);
    v.y = fmaxf(fmaf(y.y, Af, Bf), 0.0f) + fmaxf(fmaf(r.y, Ar, Br), 0.0f);
    v.z = fmaxf(fmaf(y.z, Af, Bf), 0.0f) + fmaxf(fmaf(r.z, Ar, Br), 0.0f);
    v.w = fmaxf(fmaf(y.w, Af, Bf), 0.0f) + fmaxf(fmaf(r.w, Ar, Br), 0.0f);
    ((float4*)out)[i4] = v;
}

// ---------------------------------------------------------------------------
extern "C" void kernel_launch(void* const* d_in, const int* in_sizes, int n_in,
                              void* d_out, int out_size) {
    const float* xyz   = (const float*)d_in[0];   // (1, N, 3)
    const float* pf    = (const float*)d_in[1];   // (1, 64, N)
    const float* np    = (const float*)d_in[2];   // (1, 67, N, 32)
    const float* Wint  = (const float*)d_in[3];
    const float* bint  = (const float*)d_in[4];
    const float* Wfeat = (const float*)d_in[5];
    const float* bfeat = (const float*)d_in[6];
    const float* gfeat = (const float*)d_in[7];
    const float* befeat= (const float*)d_in[8];
    const float* Wres  = (const float*)d_in[9];
    const float* bres  = (const float*)d_in[10];
    const float* gres  = (const float*)d_in[11];
    const float* beres = (const float*)d_in[12];
    float* out = (float*)d_out;

    k_zero_stats<<<1, 4 * C_OUT>>>();
    k_fused<<<N_PTS / 32, 256>>>(xyz, np, pf, Wint, bint,
                                 Wfeat, bfeat, Wres, bres);
    k_final<<<(C_OUT * N_PTS / 4) / 256, 256>>>(gfeat, befeat, gres, beres, out);
}

// round 8
// speedup vs baseline: 1.4493x; 1.4493x over previous
#include <cuda_runtime.h>
#include <cuda_bf16.h>

#define N_PTS   32768
#define S_NBR   32
#define C_IN    64
#define C_OUT   128
#define NS      (N_PTS * S_NBR)   // 1048576
#define EPSBN   1e-5f

// Scratch (device globals; no allocation allowed)
__device__ float  g_ypre[C_OUT * N_PTS];   // [o][n] 16 MB  (feature pre-BN)
__device__ float  g_rpre[C_OUT * N_PTS];   // [o][n] 16 MB  (residual pre-BN)
__device__ float2 g_part[2 * C_OUT * 4];   // partial (sum, sumsq) per (path, o, quarter)

// ---------------------------------------------------------------------------
// Fully fused kernel (R5 structure; GEMVs as two 8-output half-passes to
// lower register pressure -> 3 CTAs/SM without a forced cap).
// Block = 256 threads, 32 points.
//
// Phase 1 (aggregation): lane = (idx = lane>>3, s4 = lane&7).
//   Warp w owns channels [8w, 8w+8). Point-group outer (positions register-
//   resident), channel inner. LDG.128 per warp = 512B contiguous.
//   3-shfl reduce over the 8-lane s4 group.
// Phase 2 (feature GEMV 64->128): warp = 16-output slab done as 2x8, lane = point.
// Phase 3 (residual GEMV): same tiling, smem reloaded.
__global__ __launch_bounds__(256) void k_fused(
    const float* __restrict__ xyz,     // [N][3]
    const float* __restrict__ np,      // [67][N][S]
    const float* __restrict__ pf,      // [64][N]
    const float* __restrict__ Wint,    // [64][3]
    const float* __restrict__ bint,    // [64]
    const float* __restrict__ Wfeat,   // [128][64]
    const float* __restrict__ bfeat,   // [128]
    const float* __restrict__ Wres,    // [128][64]
    const float* __restrict__ bres)    // [128]
{
    __shared__ __align__(16) float spos[3 * 32 * 32];  // 12 KB: [k][pt][s]
    __shared__ float  aggs[C_IN][33];                  // padded; reused as pf tile
    __shared__ float4 Ws[C_OUT * (C_IN/4)];            // 32 KB
    __shared__ float  bs[C_OUT];
    __shared__ float4 wq[C_IN];                        // {w0,w1,w2,bias}

    int tid  = threadIdx.x;
    int warp = tid >> 5;
    int lane = tid & 31;
    int n0   = blockIdx.x * 32;

    // ---- stage Wint + Wfeat + relative positions ----
    if (tid < C_IN)
        wq[tid] = make_float4(Wint[tid*3+0], Wint[tid*3+1], Wint[tid*3+2], bint[tid]);
    {
        const float4* W4 = (const float4*)Wfeat;
        #pragma unroll
        for (int i = tid; i < C_OUT * (C_IN/4); i += 256) Ws[i] = W4[i];
        if (tid < C_OUT) bs[tid] = bfeat[tid];
    }
    #pragma unroll
    for (int i = tid; i < 3 * 1024; i += 256) {
        int k  = i >> 10;          // coord 0..2
        int r  = i & 1023;         // pt*32 + s
        int pt = r >> 5;
        spos[i] = np[k * NS + (n0 << 5) + r] - xyz[(n0 + pt) * 3 + k];
    }
    __syncthreads();

    // ---- Phase 1: aggregation (positions register-resident) ----
    {
        int s4  = lane & 7;        // 16B chunk within a 128B s-line
        int idx = lane >> 3;       // point within group of 4
        int c0  = warp << 3;       // first channel this warp owns
        const float4* sp4 = (const float4*)spos;

        #pragma unroll
        for (int ptg = 0; ptg < 8; ptg++) {
            int pt = (ptg << 2) | idx;
            float4 px = sp4[0 * 256 + (pt << 3) + s4];
            float4 py = sp4[1 * 256 + (pt << 3) + s4];
            float4 pz = sp4[2 * 256 + (pt << 3) + s4];

            const float* fb = np + (size_t)3 * NS
                            + (((size_t)(n0 + pt)) << 5) + (s4 << 2);

            #pragma unroll
            for (int ci = 0; ci < 8; ci++) {
                int c = c0 | ci;
                float4 w = wq[c];                                  // broadcast
                float4 f = *(const float4*)(fb + (size_t)c * NS);  // 512B/warp

                float h0 = fmaf(w.x, px.x, fmaf(w.y, py.x, fmaf(w.z, pz.x, w.w)));
                float h1 = fmaf(w.x, px.y, fmaf(w.y, py.y, fmaf(w.z, pz.y, w.w)));
                float h2 = fmaf(w.x, px.z, fmaf(w.y, py.z, fmaf(w.z, pz.z, w.w)));
                float h3 = fmaf(w.x, px.w, fmaf(w.y, py.w, fmaf(w.z, pz.w, w.w)));

                float acc;
                acc = fmaxf(h0, 0.0f) * f.x;
                acc = fmaf(fmaxf(h1, 0.0f), f.y, acc);
                acc = fmaf(fmaxf(h2, 0.0f), f.z, acc);
                acc = fmaf(fmaxf(h3, 0.0f), f.w, acc);

                acc += __shfl_xor_sync(0xffffffffu, acc, 1);
                acc += __shfl_xor_sync(0xffffffffu, acc, 2);
                acc += __shfl_xor_sync(0xffffffffu, acc, 4);
                if (s4 == 0) aggs[c][pt] = acc;
            }
        }
    }
    __syncthreads();

    // ---- Phase 2: feature GEMV (two 8-output half-passes) ----
    {
        int n = n0 + lane;
        #pragma unroll
        for (int half = 0; half < 2; half++) {
            int o0 = warp * 16 + half * 8;
            float acc[8];
            #pragma unroll
            for (int oi = 0; oi < 8; oi++) acc[oi] = bs[o0 + oi];

            #pragma unroll 4
            for (int c4 = 0; c4 < C_IN/4; c4++) {
                float f0 = aggs[c4*4+0][lane];
                float f1 = aggs[c4*4+1][lane];
                float f2 = aggs[c4*4+2][lane];
                float f3 = aggs[c4*4+3][lane];
                #pragma unroll
                for (int oi = 0; oi < 8; oi++) {
                    float4 w4 = Ws[(o0 + oi) * (C_IN/4) + c4];
                    acc[oi] = fmaf(f0, w4.x, acc[oi]);
                    acc[oi] = fmaf(f1, w4.y, acc[oi]);
                    acc[oi] = fmaf(f2, w4.z, acc[oi]);
                    acc[oi] = fmaf(f3, w4.w, acc[oi]);
                }
            }
            #pragma unroll
            for (int oi = 0; oi < 8; oi++)
                g_ypre[(o0 + oi) * N_PTS + n] = acc[oi];   // coalesced
        }
    }
    __syncthreads();   // done reading aggs/Ws before overwrite

    // ---- reload smem with residual operands ----
    {
        const float4* W4 = (const float4*)Wres;
        #pragma unroll
        for (int i = tid; i < C_OUT * (C_IN/4); i += 256) Ws[i] = W4[i];
        if (tid < C_OUT) bs[tid] = bres[tid];
    }
    #pragma unroll
    for (int i = tid; i < C_IN * 32; i += 256) {
        int cc = i >> 5, col = i & 31;
        aggs[cc][col] = pf[cc * N_PTS + n0 + col];   // coalesced
    }
    __syncthreads();

    // ---- Phase 3: residual GEMV (two 8-output half-passes) ----
    {
        int n = n0 + lane;
        #pragma unroll
        for (int half = 0; half < 2; half++) {
            int o0 = warp * 16 + half * 8;
            float acc[8];
            #pragma unroll
            for (int oi = 0; oi < 8; oi++) acc[oi] = bs[o0 + oi];

            #pragma unroll 4
            for (int c4 = 0; c4 < C_IN/4; c4++) {
                float f0 = aggs[c4*4+0][lane];
                float f1 = aggs[c4*4+1][lane];
                float f2 = aggs[c4*4+2][lane];
                float f3 = aggs[c4*4+3][lane];
                #pragma unroll
                for (int oi = 0; oi < 8; oi++) {
                    float4 w4 = Ws[(o0 + oi) * (C_IN/4) + c4];
                    acc[oi] = fmaf(f0, w4.x, acc[oi]);
                    acc[oi] = fmaf(f1, w4.y, acc[oi]);
                    acc[oi] = fmaf(f2, w4.z, acc[oi]);
                    acc[oi] = fmaf(f3, w4.w, acc[oi]);
                }
            }
            #pragma unroll
            for (int oi = 0; oi < 8; oi++)
                g_rpre[(o0 + oi) * N_PTS + n] = acc[oi];
        }
    }
}

// ---------------------------------------------------------------------------
// BN partial stats: 1024 blocks = (path, channel, quarter-row). No atomics.
__global__ __launch_bounds__(256) void k_stats(void)
{
    __shared__ float ws1[8], ws2[8];

    int bid  = blockIdx.x;
    int q    = bid & 3;
    int o    = (bid >> 2) & (C_OUT - 1);
    int path = bid >> 9;
    int tid  = threadIdx.x;

    const float4* src = (const float4*)((path ? g_rpre : g_ypre) + o * N_PTS)
                      + q * (N_PTS / 16);

    float s1 = 0.0f, s2 = 0.0f;
    #pragma unroll
    for (int i = tid; i < N_PTS/16; i += 256) {
        float4 v = src[i];
        s1 += v.x + v.y + v.z + v.w;
        s2 += v.x*v.x + v.y*v.y + v.z*v.z + v.w*v.w;
    }
    #pragma unroll
    for (int off = 16; off; off >>= 1) {
        s1 += __shfl_xor_sync(0xffffffffu, s1, off);
        s2 += __shfl_xor_sync(0xffffffffu, s2, off);
    }
    int warp = tid >> 5, lane = tid & 31;
    if (lane == 0) { ws1[warp] = s1; ws2[warp] = s2; }
    __syncthreads();
    if (tid == 0) {
        float t1 = 0.0f, t2 = 0.0f;
        #pragma unroll
        for (int w = 0; w < 8; w++) { t1 += ws1[w]; t2 += ws2[w]; }
        g_part[bid] = make_float2(t1, t2);
    }
}

// ---------------------------------------------------------------------------
// Finalize: reduce partials + BN coefficients inline, affine + ReLU both
// paths, add, float4 throughout.
__global__ __launch_bounds__(256) void k_final(
    const float* __restrict__ gf, const float* __restrict__ btf,
    const float* __restrict__ gr, const float* __restrict__ btr,
    float* __restrict__ out)
{
    int i4 = blockIdx.x * 256 + threadIdx.x;    // float4 index
    int o  = i4 >> 13;                          // channel (N/4 = 8192 per row)
    const float inv = 1.0f / (float)N_PTS;

    float s1f = 0.0f, s2f = 0.0f, s1r = 0.0f, s2r = 0.0f;
    #pragma unroll
    for (int q = 0; q < 4; q++) {
        float2 pF = g_part[(o << 2) + q];                    // cached/broadcast
        float2 pR = g_part[(1 << 9) + (o << 2) + q];
        s1f += pF.x; s2f += pF.y;
        s1r += pR.x; s2r += pR.y;
    }

    float mf = s1f * inv;
    float vf = s2f * inv - mf * mf;
    float Af = gf[o] * rsqrtf(vf + EPSBN);
    float Bf = btf[o] - mf * Af;

    float mr = s1r * inv;
    float vr = s2r * inv - mr * mr;
    float Ar = gr[o] * rsqrtf(vr + EPSBN);
    float Br = btr[o] - mr * Ar;

    float4 y = ((const float4*)g_ypre)[i4];
    float4 r = ((const float4*)g_rpre)[i4];
    float4 v;
    v.x = fmaxf(fmaf(y.x, Af, Bf), 0.0f) + fmaxf(fmaf(r.x, Ar, Br), 0.0f);
    v.y = fmaxf(fmaf(y.y, Af, Bf), 0.0f) + fmaxf(fmaf(r.y, Ar, Br), 0.0f);
    v.z = fmaxf(fmaf(y.z, Af, Bf), 0.0f) + fmaxf(fmaf(r.z, Ar, Br), 0.0f);
    v.w = fmaxf(fmaf(y.w, Af, Bf), 0.0f) + fmaxf(fmaf(r.w, Ar, Br), 0.0f);
    ((float4*)out)[i4] = v;
}

// ---------------------------------------------------------------------------
extern "C" void kernel_launch(void* const* d_in, const int* in_sizes, int n_in,
                              void* d_out, int out_size) {
    const float* xyz   = (const float*)d_in[0];   // (1, N, 3)
    const float* pf    = (const float*)d_in[1];   // (1, 64, N)
    const float* np    = (const float*)d_in[2];   // (1, 67, N, 32)
    const float* Wint  = (const float*)d_in[3];
    const float* bint  = (const float*)d_in[4];
    const float* Wfeat = (const float*)d_in[5];
    const float* bfeat = (const float*)d_in[6];
    const float* gfeat = (const float*)d_in[7];
    const float* befeat= (const float*)d_in[8];
    const float* Wres  = (const float*)d_in[9];
    const float* bres  = (const float*)d_in[10];
    const float* gres  = (const float*)d_in[11];
    const float* beres = (const float*)d_in[12];
    float* out = (float*)d_out;

    k_fused<<<N_PTS / 32, 256>>>(xyz, np, pf, Wint, bint,
                                 Wfeat, bfeat, Wres, bres);
    k_stats<<<2 * C_OUT * 4, 256>>>();
    k_final<<<(C_OUT * N_PTS / 4) / 256, 256>>>(gfeat, befeat, gres, beres, out);
}